// round 12
// baseline (speedup 1.0000x reference)
#include <cuda_runtime.h>
#include <cuda_bf16.h>
#include <cstdint>

// ChannelPruner: out[b,o,h,w] = sum_c w[o,c] * x[b,c,h,w]
// x: (32, 256, 56, 56) fp32; w: (256,256,1,1) fp32, sparse rows discovered at
// runtime (correct for ANY w).
//
// R12: fully bulk-async data path. Per (b,o)-plane block:
//   TMA bulk load (cp.async.bulk G2S, one 12544B transaction) -> smem
//   register accumulate via LDS.128 (thread-private slots)
//   STS back into the same buffer (slots are thread-private -> no hazard)
//   TMA bulk store (proven R10 epilogue)
// Both streams ride the TMA engine's deep queue of large sequential
// transfers instead of 512B warp-scheduled LDG/STG bursts.

#define N_CH        256
#define BATCH       32
#define HW4         784                   // (56*56)/4 float4 per plane
#define NPLANE      (BATCH * N_CH)        // 8192 blocks
#define PLANE_BYTES (HW4 * 16)            // 12544 B

__device__ __forceinline__ uint32_t smem_u32(const void* p) {
    uint32_t a;
    asm("{ .reg .u64 t; cvta.to.shared.u64 t, %1; cvt.u32.u64 %0, t; }"
        : "=r"(a) : "l"(p));
    return a;
}

__global__ __launch_bounds__(256, 8) void prune_fused(const float4* __restrict__ x,
                                                      const float*  __restrict__ w,
                                                      float4* __restrict__ out) {
    __shared__ alignas(128) float4 s_buf[HW4];    // 12544 B in/out staging
    __shared__ alignas(8) uint64_t s_mbar;
    __shared__ int   s_cols[N_CH];
    __shared__ float s_vals[N_CH];
    __shared__ int   s_warp_off[9];

    const int tid  = threadIdx.x;
    const int lane = tid & 31;
    const int wid  = tid >> 5;

    const int bo = blockIdx.x;        // plane index b*256 + o
    const int o  = bo & (N_CH - 1);

    const uint32_t mbar = smem_u32(&s_mbar);
    const uint32_t sbuf = smem_u32(s_buf);

    if (tid == 0) {
        asm volatile("mbarrier.init.shared.b64 [%0], 1;" :: "r"(mbar) : "memory");
    }

    // ---- prologue: deterministic compaction of w row o (proven) ----
    const float wv = __ldg(&w[o * N_CH + tid]);
    const unsigned mask = __ballot_sync(0xffffffffu, wv != 0.0f);
    if (lane == 0) s_warp_off[wid + 1] = __popc(mask);
    __syncthreads();   // also publishes mbarrier.init
    if (tid == 0) {
        int acc = 0;
        s_warp_off[0] = 0;
#pragma unroll
        for (int i = 0; i < 8; i++) { acc += s_warp_off[i + 1]; s_warp_off[i + 1] = acc; }
    }
    __syncthreads();
    if (wv != 0.0f) {
        const int pos = s_warp_off[wid] + __popc(mask & ((1u << lane) - 1u));
        s_cols[pos] = tid;
        s_vals[pos] = wv;
    }
    __syncthreads();

    const int nnz = s_warp_off[8];

    // ---- body: TMA-load each needed plane, accumulate in registers ----
    float4 z = make_float4(0.f, 0.f, 0.f, 0.f);
    float4 a0 = z, a1 = z, a2 = z, a3 = z;

    const float4* xb = x + (size_t)(bo >> 8) * (N_CH * HW4);
    const bool tail = tid < (HW4 - 768);          // tid < 16
    int phase = 0;

    for (int j = 0; j < nnz; j++) {
        if (j > 0) __syncthreads();               // all reads of prev plane done

        if (tid == 0) {
            const float4* src = xb + (size_t)s_cols[j] * HW4;
            asm volatile(
                "mbarrier.arrive.expect_tx.shared.b64 _, [%0], %1;"
                :: "r"(mbar), "r"((uint32_t)PLANE_BYTES) : "memory");
            asm volatile(
                "cp.async.bulk.shared::cta.global.mbarrier::complete_tx::bytes "
                "[%0], [%1], %2, [%3];"
                :: "r"(sbuf), "l"(src), "r"((uint32_t)PLANE_BYTES), "r"(mbar)
                : "memory");
        }

        // all threads wait for the plane
        {
            uint32_t done;
            asm volatile(
                "{\n\t.reg .pred p;\n\t"
                "mbarrier.try_wait.parity.acquire.cta.shared::cta.b64 p, [%1], %2;\n\t"
                "selp.b32 %0, 1, 0, p;\n\t}"
                : "=r"(done) : "r"(mbar), "r"((uint32_t)phase) : "memory");
            if (!done) {
                asm volatile(
                    "{\n\t.reg .pred P1;\n\t"
                    "W_%=:\n\t"
                    "mbarrier.try_wait.parity.acquire.cta.shared::cta.b64 P1, [%0], %1, 0x989680;\n\t"
                    "@P1 bra.uni D_%=;\n\t"
                    "bra.uni W_%=;\n\t"
                    "D_%=:\n\t}"
                    :: "r"(mbar), "r"((uint32_t)phase) : "memory");
            }
        }
        phase ^= 1;

        const float v = s_vals[j];
        const float4 r0 = s_buf[tid];
        const float4 r1 = s_buf[tid + 256];
        const float4 r2 = s_buf[tid + 512];
        float4 r3 = z;
        if (tail) r3 = s_buf[tid + 768];

        a0.x += v * r0.x; a0.y += v * r0.y; a0.z += v * r0.z; a0.w += v * r0.w;
        a1.x += v * r1.x; a1.y += v * r1.y; a1.z += v * r1.z; a1.w += v * r1.w;
        a2.x += v * r2.x; a2.y += v * r2.y; a2.z += v * r2.z; a2.w += v * r2.w;
        if (tail) {
            a3.x += v * r3.x; a3.y += v * r3.y; a3.z += v * r3.z; a3.w += v * r3.w;
        }
    }

    // ---- epilogue: thread-private STS into same buffer, then TMA store ----
    s_buf[tid]       = a0;
    s_buf[tid + 256] = a1;
    s_buf[tid + 512] = a2;
    if (tail) s_buf[tid + 768] = a3;
    __syncthreads();

    if (tid == 0) {
        asm volatile("fence.proxy.async.shared::cta;" ::: "memory");
        float4* dst = out + (size_t)bo * HW4;
        asm volatile(
            "cp.async.bulk.global.shared::cta.bulk_group [%0], [%1], %2;"
            :: "l"(dst), "r"(sbuf), "r"((uint32_t)PLANE_BYTES) : "memory");
        asm volatile("cp.async.bulk.commit_group;" ::: "memory");
        asm volatile("cp.async.bulk.wait_group.read 0;" ::: "memory");
    }
}

extern "C" void kernel_launch(void* const* d_in, const int* in_sizes, int n_in,
                              void* d_out, int out_size) {
    const float4* x = (const float4*)d_in[0];
    const float*  w = (const float*)d_in[1];
    float4* out = (float4*)d_out;

    prune_fused<<<NPLANE, 256>>>(x, w, out);
}